// round 13
// baseline (speedup 1.0000x reference)
#include <cuda_runtime.h>
#include <cuda_fp16.h>
#include <math.h>

#define N_NODES 100000
#define N_EDGES 1000000
#define EQ      (N_EDGES / 4)
#define F 32
#define DFEAT 160            // 5 segments x 32
#define BM 128               // GEMM M tile
#define NHF4 (N_NODES * F / 8)   // float4 count per fp16 [N,F] array = 400000

// ---------------- scratch (device globals; no allocation) ----------------
__device__ __align__(16) float  g_deg[2 * N_NODES];        // [deg_out | deg_in]
__device__ __align__(16) int4   g_eP[N_EDGES];             // {src, dst, no_bits, ni_bits}
__device__ __align__(16) __half g_T1o16[N_NODES * F];      // fp16 accumulators (hop 1)
__device__ __align__(16) __half g_T1i16[N_NODES * F];
__device__ __align__(16) __half g_P2o16[N_NODES * F];      // fp16 accumulators (hop 2)
__device__ __align__(16) __half g_P2i16[N_NODES * F];
__device__ __align__(16) float  g_W[DFEAT * 64];           // [f][64]: cols 0-31 Wz_eff, 32-63 Wh_eff

// ---------------- helpers ----------------
// 16-byte fp16 vector reduction: adds 8 halves in one L2 atomic op (sm_90+)
__device__ __forceinline__ void red4h(__half* p, __half2 a, __half2 b, __half2 c, __half2 d) {
    unsigned ua = *(unsigned*)&a, ub = *(unsigned*)&b, uc = *(unsigned*)&c, ud = *(unsigned*)&d;
    asm volatile("red.global.add.noftz.v4.f16x2 [%0], {%1,%2,%3,%4};"
                 :: "l"(p), "r"(ua), "r"(ub), "r"(uc), "r"(ud) : "memory");
}
__device__ __forceinline__ float tf32r(float x) {
    unsigned u;
    asm("cvt.rna.tf32.f32 %0, %1;" : "=r"(u) : "f"(x));
    return __uint_as_float(u);
}
__device__ __forceinline__ void mma_tf32(float c[4], unsigned a0, unsigned a1, unsigned a2,
                                         unsigned a3, unsigned b0, unsigned b1) {
    asm("mma.sync.aligned.m16n8k8.row.col.f32.tf32.tf32.f32 "
        "{%0,%1,%2,%3}, {%4,%5,%6,%7}, {%8,%9}, {%0,%1,%2,%3};"
        : "+f"(c[0]), "+f"(c[1]), "+f"(c[2]), "+f"(c[3])
        : "r"(a0), "r"(a1), "r"(a2), "r"(a3), "r"(b0), "r"(b1));
}
__device__ __forceinline__ float4 unpack4h(float2 r) { // 4 halves (as float2 bits) -> 4 floats
    __half2 h01 = *(__half2*)&r.x;
    __half2 h23 = *(__half2*)&r.y;
    float2 f01 = __half22float2(h01);
    float2 f23 = __half22float2(h23);
    return make_float4(f01.x, f01.y, f23.x, f23.y);
}

// ---------------- kernels ----------------
// zero all fp16 accumulators + deg
__global__ void prep_kernel() {
    int i = blockIdx.x * blockDim.x + threadIdx.x;   // float4 index
    if (i >= NHF4) return;
    float4 z = make_float4(0.f, 0.f, 0.f, 0.f);
    ((float4*)g_T1o16)[i] = z;
    ((float4*)g_T1i16)[i] = z;
    ((float4*)g_P2o16)[i] = z;
    ((float4*)g_P2i16)[i] = z;
    if (i < (2 * N_NODES) / 4) ((float4*)g_deg)[i] = z;
}

__global__ void deg_kernel(const int* __restrict__ src, const int* __restrict__ dst,
                           const float* __restrict__ ew) {
    int e = blockIdx.x * blockDim.x + threadIdx.x;
    if (e >= N_EDGES) return;
    float w = ew[e];
    atomicAdd(&g_deg[src[e]], w);
    atomicAdd(&g_deg[N_NODES + dst[e]], w);
}

// pack {src, dst, norm_out, norm_in} per edge (one 16B record)
__global__ void pack_kernel(const int* __restrict__ src, const int* __restrict__ dst,
                            const float* __restrict__ ew) {
    int e = blockIdx.x * blockDim.x + threadIdx.x;
    if (e >= N_EDGES) return;
    int s = src[e], d = dst[e];
    float w = ew[e];
    float no = w / g_deg[s];
    float ni = w / g_deg[N_NODES + d];
    g_eP[e] = make_int4(s, d, __float_as_int(no), __float_as_int(ni));
}

// hop 1, ILP=4: each thread handles edges e0 + k*EQ (k=0..3) with the same (dir,lane) role.
// Per thread: 4 edge LDG.128 -> 8 gather LDG.128 -> 4 vector-reds (loads independent).
__global__ void prop1_kernel(const float* __restrict__ X) {
    long idx = (long)blockIdx.x * blockDim.x + threadIdx.x;
    int e0 = (int)(idx >> 3);
    if (e0 >= EQ) return;
    int h = (int)(idx & 7);
    int dir = h >> 2, l = h & 3;

    int4 ep[4];
#pragma unroll
    for (int k = 0; k < 4; k++) ep[k] = g_eP[e0 + k * EQ];

    if (dir == 0) {
        float4 v0[4], v1[4];
#pragma unroll
        for (int k = 0; k < 4; k++) {
            v0[k] = ((const float4*)X)[ep[k].x * 8 + 2 * l];
            v1[k] = ((const float4*)X)[ep[k].x * 8 + 2 * l + 1];
        }
#pragma unroll
        for (int k = 0; k < 4; k++) {
            float no = __int_as_float(ep[k].z);
            red4h(&g_T1o16[ep[k].y * F + 8 * l],
                  __floats2half2_rn(v0[k].x * no, v0[k].y * no),
                  __floats2half2_rn(v0[k].z * no, v0[k].w * no),
                  __floats2half2_rn(v1[k].x * no, v1[k].y * no),
                  __floats2half2_rn(v1[k].z * no, v1[k].w * no));
        }
    } else {
        float4 v0[4], v1[4];
#pragma unroll
        for (int k = 0; k < 4; k++) {
            v0[k] = ((const float4*)X)[ep[k].y * 8 + 2 * l];
            v1[k] = ((const float4*)X)[ep[k].y * 8 + 2 * l + 1];
        }
#pragma unroll
        for (int k = 0; k < 4; k++) {
            float ni = __int_as_float(ep[k].w);
            red4h(&g_T1i16[ep[k].x * F + 8 * l],
                  __floats2half2_rn(v0[k].x * ni, v0[k].y * ni),
                  __floats2half2_rn(v0[k].z * ni, v0[k].w * ni),
                  __floats2half2_rn(v1[k].x * ni, v1[k].y * ni),
                  __floats2half2_rn(v1[k].z * ni, v1[k].w * ni));
        }
    }
}

// hop 2, ILP=4: fp16 gathers (one 16B load = 8 features), same 4-edge structure.
__global__ void prop2_kernel() {
    long idx = (long)blockIdx.x * blockDim.x + threadIdx.x;
    int e0 = (int)(idx >> 3);
    if (e0 >= EQ) return;
    int h = (int)(idx & 7);
    int dir = h >> 2, l = h & 3;

    int4 ep[4];
#pragma unroll
    for (int k = 0; k < 4; k++) ep[k] = g_eP[e0 + k * EQ];

    if (dir == 0) {
        float4 r[4];
#pragma unroll
        for (int k = 0; k < 4; k++) r[k] = ((const float4*)g_T1o16)[ep[k].x * 4 + l];
#pragma unroll
        for (int k = 0; k < 4; k++) {
            float no = __int_as_float(ep[k].z);
            float4 f01 = unpack4h(make_float2(r[k].x, r[k].y));
            float4 f23 = unpack4h(make_float2(r[k].z, r[k].w));
            red4h(&g_P2o16[ep[k].y * F + 8 * l],
                  __floats2half2_rn(f01.x * no, f01.y * no),
                  __floats2half2_rn(f01.z * no, f01.w * no),
                  __floats2half2_rn(f23.x * no, f23.y * no),
                  __floats2half2_rn(f23.z * no, f23.w * no));
        }
    } else {
        float4 r[4];
#pragma unroll
        for (int k = 0; k < 4; k++) r[k] = ((const float4*)g_T1i16)[ep[k].y * 4 + l];
#pragma unroll
        for (int k = 0; k < 4; k++) {
            float ni = __int_as_float(ep[k].w);
            float4 f01 = unpack4h(make_float2(r[k].x, r[k].y));
            float4 f23 = unpack4h(make_float2(r[k].z, r[k].w));
            red4h(&g_P2i16[ep[k].x * F + 8 * l],
                  __floats2half2_rn(f01.x * ni, f01.y * ni),
                  __floats2half2_rn(f01.z * ni, f01.w * ni),
                  __floats2half2_rn(f23.x * ni, f23.y * ni),
                  __floats2half2_rn(f23.z * ni, f23.w * ni));
        }
    }
}

// Build W_eff[160][64].  W layout: [2][3][64][32], only rows <32 matter (H-half is zero).
__global__ void wprep_kernel(const float* __restrict__ Wz, const float* __restrict__ Wh) {
    int idx = blockIdx.x * blockDim.x + threadIdx.x;
    if (idx >= 2 * DFEAT * F) return;
    int gate = idx / (DFEAT * F);
    int rem  = idx % (DFEAT * F);
    int f = rem / F, j = rem % F;
    int seg = f >> 5, r = f & 31;
    const float* W = gate ? Wh : Wz;
    float v;
    if (seg == 0)      v = W[(0 * 64 + r) * 32 + j] + W[(3 * 64 + r) * 32 + j]
                         - W[(2 * 64 + r) * 32 + j] - W[(5 * 64 + r) * 32 + j];
    else if (seg == 1) v = W[(1 * 64 + r) * 32 + j];
    else if (seg == 2) v = W[(4 * 64 + r) * 32 + j];
    else if (seg == 3) v = 2.f * W[(2 * 64 + r) * 32 + j];
    else               v = 2.f * W[(5 * 64 + r) * 32 + j];
    g_W[f * 64 + gate * 32 + j] = v;
}

// ---------------- tensor-core GEMM + fused GRU epilogue ----------------
// [BM x 160] @ [160 x 64] via mma.sync.m16n8k8.tf32. Seg 0 = X fp32 (tf32-rounded);
// segs 1-4 read fp16 accumulators directly (fp16 -> tf32 exact).
__global__ __launch_bounds__(128) void gemm_kernel(
    const float* __restrict__ X,
    const float* __restrict__ bz, const float* __restrict__ bh,
    const float* __restrict__ wl, const float* __restrict__ bl,
    float* __restrict__ out)
{
    __shared__ __align__(16) float As[BM][36];   // [m][k]
    __shared__ __align__(16) float Bs[32][72];   // [k][n]

    int tid  = threadIdx.x;
    int w    = tid >> 5;
    int lane = tid & 31;
    int g    = lane >> 2;      // 0..7
    int tg   = lane & 3;       // 0..3
    int blockm = blockIdx.x * BM;

    float c[2][8][4];
#pragma unroll
    for (int mf = 0; mf < 2; mf++)
#pragma unroll
        for (int n = 0; n < 8; n++)
#pragma unroll
            for (int k = 0; k < 4; k++) c[mf][n][k] = 0.f;

    const __half* seg16[5] = { 0, g_T1o16, g_T1i16, g_P2o16, g_P2i16 };

    for (int ks = 0; ks < 5; ks++) {
        // A tile: 128 nodes x 32 feats
#pragma unroll
        for (int i = 0; i < 8; i++) {
            int idx = i * 128 + tid;          // 0..1023
            int m  = idx >> 3;
            int f4 = idx & 7;
            int node = blockm + m;
            float4 t;
            if (ks == 0) {
                float4 v = (node < N_NODES) ? ((const float4*)X)[node * 8 + f4]
                                            : make_float4(0.f, 0.f, 0.f, 0.f);
                t = make_float4(tf32r(v.x), tf32r(v.y), tf32r(v.z), tf32r(v.w));
            } else {
                float2 r = (node < N_NODES) ? ((const float2*)seg16[ks])[node * 8 + f4]
                                            : make_float2(0.f, 0.f);
                t = unpack4h(r);              // fp16 -> tf32 exact
            }
            *(float4*)&As[m][f4 * 4] = t;
        }
        // B tile: 32 x 64, tf32-rounded
#pragma unroll
        for (int i = 0; i < 4; i++) {
            int fidx = i * 128 + tid;         // float4 idx, 0..511
            float4 v = ((const float4*)g_W)[ks * 512 + fidx];
            int r  = fidx >> 4;
            int c4 = (fidx & 15) * 4;
            float4 t = make_float4(tf32r(v.x), tf32r(v.y), tf32r(v.z), tf32r(v.w));
            *(float4*)&Bs[r][c4] = t;
        }
        __syncthreads();

#pragma unroll
        for (int kst = 0; kst < 4; kst++) {
            int kb = kst * 8;
            unsigned a[2][4];
#pragma unroll
            for (int mf = 0; mf < 2; mf++) {
                int mb = w * 32 + mf * 16;
                a[mf][0] = __float_as_uint(As[mb + g    ][kb + tg    ]);
                a[mf][1] = __float_as_uint(As[mb + g + 8][kb + tg    ]);
                a[mf][2] = __float_as_uint(As[mb + g    ][kb + tg + 4]);
                a[mf][3] = __float_as_uint(As[mb + g + 8][kb + tg + 4]);
            }
#pragma unroll
            for (int n = 0; n < 8; n++) {
                unsigned b0 = __float_as_uint(Bs[kb + tg    ][n * 8 + g]);
                unsigned b1 = __float_as_uint(Bs[kb + tg + 4][n * 8 + g]);
                mma_tf32(c[0][n], a[0][0], a[0][1], a[0][2], a[0][3], b0, b1);
                mma_tf32(c[1][n], a[1][0], a[1][1], a[1][2], a[1][3], b0, b1);
            }
        }
        __syncthreads();
    }

    // epilogue. col = n*8 + 2*tg + cc; rows g / g+8.  n<4: z gates, n+4: matching h gates.
    float bzv[4][2], bhv[4][2], wlv[4][2];
#pragma unroll
    for (int n = 0; n < 4; n++)
#pragma unroll
        for (int cc = 0; cc < 2; cc++) {
            int col = n * 8 + 2 * tg + cc;
            bzv[n][cc] = bz[col];
            bhv[n][cc] = bh[col];
            wlv[n][cc] = wl[col];
        }
    float bl0 = bl[0];

#pragma unroll
    for (int mf = 0; mf < 2; mf++) {
#pragma unroll
        for (int rh = 0; rh < 2; rh++) {
            float y = 0.f;
#pragma unroll
            for (int n = 0; n < 4; n++) {
#pragma unroll
                for (int cc = 0; cc < 2; cc++) {
                    float gz = c[mf][n    ][rh * 2 + cc] + bzv[n][cc];
                    float gh = c[mf][n + 4][rh * 2 + cc] + bhv[n][cc];
                    float z  = 1.f / (1.f + expf(-gz));
                    float ht = tanhf(gh);
                    float Hv = (1.f - z) * ht;
                    y += fmaxf(Hv, 0.f) * wlv[n][cc];
                }
            }
            y += __shfl_xor_sync(0xffffffffu, y, 1);
            y += __shfl_xor_sync(0xffffffffu, y, 2);
            if (tg == 0) {
                int node = blockm + w * 32 + mf * 16 + rh * 8 + g;
                if (node < N_NODES) out[node] = y + bl0;
            }
        }
    }
}

// ---------------- launch ----------------
extern "C" void kernel_launch(void* const* d_in, const int* in_sizes, int n_in,
                              void* d_out, int out_size) {
    const float* x  = (const float*)d_in[0];
    const int*   ei = (const int*)d_in[1];
    const float* ew = (const float*)d_in[2];
    const float* Wz = (const float*)d_in[5];
    const float* bz = (const float*)d_in[6];
    const float* Wh = (const float*)d_in[9];
    const float* bh = (const float*)d_in[10];
    const float* Wl = (const float*)d_in[11];
    const float* bl = (const float*)d_in[12];
    float* out = (float*)d_out;

    const int* src = ei;
    const int* dst = ei + N_EDGES;

    prep_kernel<<<(NHF4 + 255) / 256, 256>>>();
    deg_kernel<<<(N_EDGES + 255) / 256, 256>>>(src, dst, ew);
    pack_kernel<<<(N_EDGES + 255) / 256, 256>>>(src, dst, ew);
    prop1_kernel<<<(EQ * 8 + 255) / 256, 256>>>(x);
    prop2_kernel<<<(EQ * 8 + 255) / 256, 256>>>();
    wprep_kernel<<<(2 * DFEAT * F + 255) / 256, 256>>>(Wz, Wh);
    gemm_kernel<<<(N_NODES + BM - 1) / BM, 128>>>(x, bz, bh, Wl, bl, out);
}

// round 14
// speedup vs baseline: 1.0020x; 1.0020x over previous
#include <cuda_runtime.h>
#include <cuda_fp16.h>
#include <math.h>

#define N_NODES 100000
#define N_EDGES 1000000
#define EHALF   (N_EDGES / 2)
#define F 32
#define DFEAT 160            // 5 segments x 32
#define BM 128               // GEMM M tile
#define NHF4 (N_NODES * F / 8)   // float4 count per fp16 [N,F] array = 400000

// ---------------- scratch (device globals; no allocation) ----------------
__device__ __align__(16) float  g_deg[2 * N_NODES];        // [deg_out | deg_in]
__device__ __align__(16) int4   g_eP[N_EDGES];             // {src, dst, no_bits, ni_bits}
__device__ __align__(16) __half g_X16 [N_NODES * F];       // fp16 mirror of X (hop-1 gathers)
__device__ __align__(16) __half g_T1o16[N_NODES * F];      // fp16 accumulators (hop 1)
__device__ __align__(16) __half g_T1i16[N_NODES * F];
__device__ __align__(16) __half g_P2o16[N_NODES * F];      // fp16 accumulators (hop 2)
__device__ __align__(16) __half g_P2i16[N_NODES * F];
__device__ __align__(16) float  g_W[DFEAT * 64];           // [f][64]: cols 0-31 Wz_eff, 32-63 Wh_eff

// ---------------- helpers ----------------
// 16-byte fp16 vector reduction: adds 8 halves in one L2 atomic op (sm_90+)
__device__ __forceinline__ void red4h(__half* p, __half2 a, __half2 b, __half2 c, __half2 d) {
    unsigned ua = *(unsigned*)&a, ub = *(unsigned*)&b, uc = *(unsigned*)&c, ud = *(unsigned*)&d;
    asm volatile("red.global.add.noftz.v4.f16x2 [%0], {%1,%2,%3,%4};"
                 :: "l"(p), "r"(ua), "r"(ub), "r"(uc), "r"(ud) : "memory");
}
__device__ __forceinline__ float tf32r(float x) {
    unsigned u;
    asm("cvt.rna.tf32.f32 %0, %1;" : "=r"(u) : "f"(x));
    return __uint_as_float(u);
}
__device__ __forceinline__ void mma_tf32(float c[4], unsigned a0, unsigned a1, unsigned a2,
                                         unsigned a3, unsigned b0, unsigned b1) {
    asm("mma.sync.aligned.m16n8k8.row.col.f32.tf32.tf32.f32 "
        "{%0,%1,%2,%3}, {%4,%5,%6,%7}, {%8,%9}, {%0,%1,%2,%3};"
        : "+f"(c[0]), "+f"(c[1]), "+f"(c[2]), "+f"(c[3])
        : "r"(a0), "r"(a1), "r"(a2), "r"(a3), "r"(b0), "r"(b1));
}
__device__ __forceinline__ float4 unpack4h(float2 r) { // 4 halves (as float2 bits) -> 4 floats
    __half2 h01 = *(__half2*)&r.x;
    __half2 h23 = *(__half2*)&r.y;
    float2 f01 = __half22float2(h01);
    float2 f23 = __half22float2(h23);
    return make_float4(f01.x, f01.y, f23.x, f23.y);
}
__device__ __forceinline__ float2 pack4h(float4 v) {   // 4 floats -> 4 halves as float2 bits
    __half2 p01 = __floats2half2_rn(v.x, v.y);
    __half2 p23 = __floats2half2_rn(v.z, v.w);
    float2 r;
    r.x = __uint_as_float(*(unsigned*)&p01);
    r.y = __uint_as_float(*(unsigned*)&p23);
    return r;
}

// ---------------- kernels ----------------
// zero all fp16 accumulators + deg, and build fp16 mirror of X
__global__ void prep_kernel(const float* __restrict__ X) {
    int i = blockIdx.x * blockDim.x + threadIdx.x;   // float4 index
    if (i >= NHF4) return;
    float4 z = make_float4(0.f, 0.f, 0.f, 0.f);
    ((float4*)g_T1o16)[i] = z;
    ((float4*)g_T1i16)[i] = z;
    ((float4*)g_P2o16)[i] = z;
    ((float4*)g_P2i16)[i] = z;
    if (i < (2 * N_NODES) / 4) ((float4*)g_deg)[i] = z;
    float2 lo = pack4h(((const float4*)X)[2 * i]);
    float2 hi = pack4h(((const float4*)X)[2 * i + 1]);
    ((float4*)g_X16)[i] = make_float4(lo.x, lo.y, hi.x, hi.y);
}

__global__ void deg_kernel(const int* __restrict__ src, const int* __restrict__ dst,
                           const float* __restrict__ ew) {
    int e = blockIdx.x * blockDim.x + threadIdx.x;
    if (e >= N_EDGES) return;
    float w = ew[e];
    atomicAdd(&g_deg[src[e]], w);
    atomicAdd(&g_deg[N_NODES + dst[e]], w);
}

// pack {src, dst, norm_out, norm_in} per edge (one 16B record)
__global__ void pack_kernel(const int* __restrict__ src, const int* __restrict__ dst,
                            const float* __restrict__ ew) {
    int e = blockIdx.x * blockDim.x + threadIdx.x;
    if (e >= N_EDGES) return;
    int s = src[e], d = dst[e];
    float w = ew[e];
    float no = w / g_deg[s];
    float ni = w / g_deg[N_NODES + d];
    g_eP[e] = make_int4(s, d, __float_as_int(no), __float_as_int(ni));
}

// hop 1, ILP=2, fp16 gathers from X16 — byte-level clone of prop2's proven shape.
__global__ void prop1_kernel() {
    long idx = (long)blockIdx.x * blockDim.x + threadIdx.x;
    int e0 = (int)(idx >> 3);
    if (e0 >= EHALF) return;
    int e1 = e0 + EHALF;
    int h = (int)(idx & 7);
    int dir = h >> 2, l = h & 3;
    int4 epA = g_eP[e0];
    int4 epB = g_eP[e1];
    if (dir == 0) {
        float noA = __int_as_float(epA.z);
        float noB = __int_as_float(epB.z);
        float4 rA = ((const float4*)g_X16)[epA.x * 4 + l];
        float4 rB = ((const float4*)g_X16)[epB.x * 4 + l];
        float4 fA01 = unpack4h(make_float2(rA.x, rA.y));
        float4 fA23 = unpack4h(make_float2(rA.z, rA.w));
        float4 fB01 = unpack4h(make_float2(rB.x, rB.y));
        float4 fB23 = unpack4h(make_float2(rB.z, rB.w));
        red4h(&g_T1o16[epA.y * F + 8 * l],
              __floats2half2_rn(fA01.x * noA, fA01.y * noA),
              __floats2half2_rn(fA01.z * noA, fA01.w * noA),
              __floats2half2_rn(fA23.x * noA, fA23.y * noA),
              __floats2half2_rn(fA23.z * noA, fA23.w * noA));
        red4h(&g_T1o16[epB.y * F + 8 * l],
              __floats2half2_rn(fB01.x * noB, fB01.y * noB),
              __floats2half2_rn(fB01.z * noB, fB01.w * noB),
              __floats2half2_rn(fB23.x * noB, fB23.y * noB),
              __floats2half2_rn(fB23.z * noB, fB23.w * noB));
    } else {
        float niA = __int_as_float(epA.w);
        float niB = __int_as_float(epB.w);
        float4 rA = ((const float4*)g_X16)[epA.y * 4 + l];
        float4 rB = ((const float4*)g_X16)[epB.y * 4 + l];
        float4 fA01 = unpack4h(make_float2(rA.x, rA.y));
        float4 fA23 = unpack4h(make_float2(rA.z, rA.w));
        float4 fB01 = unpack4h(make_float2(rB.x, rB.y));
        float4 fB23 = unpack4h(make_float2(rB.z, rB.w));
        red4h(&g_T1i16[epA.x * F + 8 * l],
              __floats2half2_rn(fA01.x * niA, fA01.y * niA),
              __floats2half2_rn(fA01.z * niA, fA01.w * niA),
              __floats2half2_rn(fA23.x * niA, fA23.y * niA),
              __floats2half2_rn(fA23.z * niA, fA23.w * niA));
        red4h(&g_T1i16[epB.x * F + 8 * l],
              __floats2half2_rn(fB01.x * niB, fB01.y * niB),
              __floats2half2_rn(fB01.z * niB, fB01.w * niB),
              __floats2half2_rn(fB23.x * niB, fB23.y * niB),
              __floats2half2_rn(fB23.z * niB, fB23.w * niB));
    }
}

// hop 2, ILP=2: fp16 gathers (one 16B load = 8 features) — unchanged from R12.
__global__ void prop2_kernel() {
    long idx = (long)blockIdx.x * blockDim.x + threadIdx.x;
    int e0 = (int)(idx >> 3);
    if (e0 >= EHALF) return;
    int e1 = e0 + EHALF;
    int h = (int)(idx & 7);
    int dir = h >> 2, l = h & 3;
    int4 epA = g_eP[e0];
    int4 epB = g_eP[e1];
    if (dir == 0) {
        float noA = __int_as_float(epA.z);
        float noB = __int_as_float(epB.z);
        float4 rA = ((const float4*)g_T1o16)[epA.x * 4 + l];
        float4 rB = ((const float4*)g_T1o16)[epB.x * 4 + l];
        float4 fA01 = unpack4h(make_float2(rA.x, rA.y));
        float4 fA23 = unpack4h(make_float2(rA.z, rA.w));
        float4 fB01 = unpack4h(make_float2(rB.x, rB.y));
        float4 fB23 = unpack4h(make_float2(rB.z, rB.w));
        red4h(&g_P2o16[epA.y * F + 8 * l],
              __floats2half2_rn(fA01.x * noA, fA01.y * noA),
              __floats2half2_rn(fA01.z * noA, fA01.w * noA),
              __floats2half2_rn(fA23.x * noA, fA23.y * noA),
              __floats2half2_rn(fA23.z * noA, fA23.w * noA));
        red4h(&g_P2o16[epB.y * F + 8 * l],
              __floats2half2_rn(fB01.x * noB, fB01.y * noB),
              __floats2half2_rn(fB01.z * noB, fB01.w * noB),
              __floats2half2_rn(fB23.x * noB, fB23.y * noB),
              __floats2half2_rn(fB23.z * noB, fB23.w * noB));
    } else {
        float niA = __int_as_float(epA.w);
        float niB = __int_as_float(epB.w);
        float4 rA = ((const float4*)g_T1i16)[epA.y * 4 + l];
        float4 rB = ((const float4*)g_T1i16)[epB.y * 4 + l];
        float4 fA01 = unpack4h(make_float2(rA.x, rA.y));
        float4 fA23 = unpack4h(make_float2(rA.z, rA.w));
        float4 fB01 = unpack4h(make_float2(rB.x, rB.y));
        float4 fB23 = unpack4h(make_float2(rB.z, rB.w));
        red4h(&g_P2i16[epA.x * F + 8 * l],
              __floats2half2_rn(fA01.x * niA, fA01.y * niA),
              __floats2half2_rn(fA01.z * niA, fA01.w * niA),
              __floats2half2_rn(fA23.x * niA, fA23.y * niA),
              __floats2half2_rn(fA23.z * niA, fA23.w * niA));
        red4h(&g_P2i16[epB.x * F + 8 * l],
              __floats2half2_rn(fB01.x * niB, fB01.y * niB),
              __floats2half2_rn(fB01.z * niB, fB01.w * niB),
              __floats2half2_rn(fB23.x * niB, fB23.y * niB),
              __floats2half2_rn(fB23.z * niB, fB23.w * niB));
    }
}

// Build W_eff[160][64].  W layout: [2][3][64][32], only rows <32 matter (H-half is zero).
__global__ void wprep_kernel(const float* __restrict__ Wz, const float* __restrict__ Wh) {
    int idx = blockIdx.x * blockDim.x + threadIdx.x;
    if (idx >= 2 * DFEAT * F) return;
    int gate = idx / (DFEAT * F);
    int rem  = idx % (DFEAT * F);
    int f = rem / F, j = rem % F;
    int seg = f >> 5, r = f & 31;
    const float* W = gate ? Wh : Wz;
    float v;
    if (seg == 0)      v = W[(0 * 64 + r) * 32 + j] + W[(3 * 64 + r) * 32 + j]
                         - W[(2 * 64 + r) * 32 + j] - W[(5 * 64 + r) * 32 + j];
    else if (seg == 1) v = W[(1 * 64 + r) * 32 + j];
    else if (seg == 2) v = W[(4 * 64 + r) * 32 + j];
    else if (seg == 3) v = 2.f * W[(2 * 64 + r) * 32 + j];
    else               v = 2.f * W[(5 * 64 + r) * 32 + j];
    g_W[f * 64 + gate * 32 + j] = v;
}

// ---------------- tensor-core GEMM + fused GRU epilogue ----------------
// [BM x 160] @ [160 x 64] via mma.sync.m16n8k8.tf32. Seg 0 = X fp32 (tf32-rounded);
// segs 1-4 read fp16 accumulators directly (fp16 -> tf32 exact).
__global__ __launch_bounds__(128) void gemm_kernel(
    const float* __restrict__ X,
    const float* __restrict__ bz, const float* __restrict__ bh,
    const float* __restrict__ wl, const float* __restrict__ bl,
    float* __restrict__ out)
{
    __shared__ __align__(16) float As[BM][36];   // [m][k]
    __shared__ __align__(16) float Bs[32][72];   // [k][n]

    int tid  = threadIdx.x;
    int w    = tid >> 5;
    int lane = tid & 31;
    int g    = lane >> 2;      // 0..7
    int tg   = lane & 3;       // 0..3
    int blockm = blockIdx.x * BM;

    float c[2][8][4];
#pragma unroll
    for (int mf = 0; mf < 2; mf++)
#pragma unroll
        for (int n = 0; n < 8; n++)
#pragma unroll
            for (int k = 0; k < 4; k++) c[mf][n][k] = 0.f;

    const __half* seg16[5] = { 0, g_T1o16, g_T1i16, g_P2o16, g_P2i16 };

    for (int ks = 0; ks < 5; ks++) {
        // A tile: 128 nodes x 32 feats
#pragma unroll
        for (int i = 0; i < 8; i++) {
            int idx = i * 128 + tid;          // 0..1023
            int m  = idx >> 3;
            int f4 = idx & 7;
            int node = blockm + m;
            float4 t;
            if (ks == 0) {
                float4 v = (node < N_NODES) ? ((const float4*)X)[node * 8 + f4]
                                            : make_float4(0.f, 0.f, 0.f, 0.f);
                t = make_float4(tf32r(v.x), tf32r(v.y), tf32r(v.z), tf32r(v.w));
            } else {
                float2 r = (node < N_NODES) ? ((const float2*)seg16[ks])[node * 8 + f4]
                                            : make_float2(0.f, 0.f);
                t = unpack4h(r);              // fp16 -> tf32 exact
            }
            *(float4*)&As[m][f4 * 4] = t;
        }
        // B tile: 32 x 64, tf32-rounded
#pragma unroll
        for (int i = 0; i < 4; i++) {
            int fidx = i * 128 + tid;         // float4 idx, 0..511
            float4 v = ((const float4*)g_W)[ks * 512 + fidx];
            int r  = fidx >> 4;
            int c4 = (fidx & 15) * 4;
            float4 t = make_float4(tf32r(v.x), tf32r(v.y), tf32r(v.z), tf32r(v.w));
            *(float4*)&Bs[r][c4] = t;
        }
        __syncthreads();

#pragma unroll
        for (int kst = 0; kst < 4; kst++) {
            int kb = kst * 8;
            unsigned a[2][4];
#pragma unroll
            for (int mf = 0; mf < 2; mf++) {
                int mb = w * 32 + mf * 16;
                a[mf][0] = __float_as_uint(As[mb + g    ][kb + tg    ]);
                a[mf][1] = __float_as_uint(As[mb + g + 8][kb + tg    ]);
                a[mf][2] = __float_as_uint(As[mb + g    ][kb + tg + 4]);
                a[mf][3] = __float_as_uint(As[mb + g + 8][kb + tg + 4]);
            }
#pragma unroll
            for (int n = 0; n < 8; n++) {
                unsigned b0 = __float_as_uint(Bs[kb + tg    ][n * 8 + g]);
                unsigned b1 = __float_as_uint(Bs[kb + tg + 4][n * 8 + g]);
                mma_tf32(c[0][n], a[0][0], a[0][1], a[0][2], a[0][3], b0, b1);
                mma_tf32(c[1][n], a[1][0], a[1][1], a[1][2], a[1][3], b0, b1);
            }
        }
        __syncthreads();
    }

    // epilogue. col = n*8 + 2*tg + cc; rows g / g+8.  n<4: z gates, n+4: matching h gates.
    float bzv[4][2], bhv[4][2], wlv[4][2];
#pragma unroll
    for (int n = 0; n < 4; n++)
#pragma unroll
        for (int cc = 0; cc < 2; cc++) {
            int col = n * 8 + 2 * tg + cc;
            bzv[n][cc] = bz[col];
            bhv[n][cc] = bh[col];
            wlv[n][cc] = wl[col];
        }
    float bl0 = bl[0];

#pragma unroll
    for (int mf = 0; mf < 2; mf++) {
#pragma unroll
        for (int rh = 0; rh < 2; rh++) {
            float y = 0.f;
#pragma unroll
            for (int n = 0; n < 4; n++) {
#pragma unroll
                for (int cc = 0; cc < 2; cc++) {
                    float gz = c[mf][n    ][rh * 2 + cc] + bzv[n][cc];
                    float gh = c[mf][n + 4][rh * 2 + cc] + bhv[n][cc];
                    float z  = 1.f / (1.f + expf(-gz));
                    float ht = tanhf(gh);
                    float Hv = (1.f - z) * ht;
                    y += fmaxf(Hv, 0.f) * wlv[n][cc];
                }
            }
            y += __shfl_xor_sync(0xffffffffu, y, 1);
            y += __shfl_xor_sync(0xffffffffu, y, 2);
            if (tg == 0) {
                int node = blockm + w * 32 + mf * 16 + rh * 8 + g;
                if (node < N_NODES) out[node] = y + bl0;
            }
        }
    }
}

// ---------------- launch ----------------
extern "C" void kernel_launch(void* const* d_in, const int* in_sizes, int n_in,
                              void* d_out, int out_size) {
    const float* x  = (const float*)d_in[0];
    const int*   ei = (const int*)d_in[1];
    const float* ew = (const float*)d_in[2];
    const float* Wz = (const float*)d_in[5];
    const float* bz = (const float*)d_in[6];
    const float* Wh = (const float*)d_in[9];
    const float* bh = (const float*)d_in[10];
    const float* Wl = (const float*)d_in[11];
    const float* bl = (const float*)d_in[12];
    float* out = (float*)d_out;

    const int* src = ei;
    const int* dst = ei + N_EDGES;

    prep_kernel<<<(NHF4 + 255) / 256, 256>>>(x);
    deg_kernel<<<(N_EDGES + 255) / 256, 256>>>(src, dst, ew);
    pack_kernel<<<(N_EDGES + 255) / 256, 256>>>(src, dst, ew);
    prop1_kernel<<<(EHALF * 8 + 255) / 256, 256>>>();
    prop2_kernel<<<(EHALF * 8 + 255) / 256, 256>>>();
    wprep_kernel<<<(2 * DFEAT * F + 255) / 256, 256>>>(Wz, Wh);
    gemm_kernel<<<(N_NODES + BM - 1) / BM, 128>>>(x, bz, bh, Wl, bl, out);
}

// round 15
// speedup vs baseline: 1.0224x; 1.0203x over previous
#include <cuda_runtime.h>
#include <cuda_fp16.h>
#include <math.h>

#define N_NODES 100000
#define N_EDGES 1000000
#define EHALF   (N_EDGES / 2)
#define F 32
#define DFEAT 160            // 5 segments x 32
#define BM 128               // GEMM M tile
#define NHF4 (N_NODES * F / 8)   // float4 count per fp16 [N,F] array = 400000

// ---------------- scratch (device globals; no allocation) ----------------
__device__ __align__(16) float  g_deg[2 * N_NODES];        // [deg_out | deg_in]
__device__ __align__(16) int4   g_eP[N_EDGES];             // {src, dst, no_bits, ni_bits}
__device__ __align__(16) __half g_X16 [N_NODES * F];       // fp16 mirror of X
__device__ __align__(16) __half g_T1o16[N_NODES * F];      // fp16 accumulators (hop 1)
__device__ __align__(16) __half g_T1i16[N_NODES * F];
__device__ __align__(16) __half g_P2o16[N_NODES * F];      // fp16 accumulators (hop 2)
__device__ __align__(16) __half g_P2i16[N_NODES * F];
__device__ __align__(16) float  g_W[DFEAT * 64];           // [f][64]: cols 0-31 Wz_eff, 32-63 Wh_eff

// ---------------- helpers ----------------
// 16-byte fp16 vector reduction: adds 8 halves in one L2 atomic op (sm_90+)
__device__ __forceinline__ void red4h(__half* p, __half2 a, __half2 b, __half2 c, __half2 d) {
    unsigned ua = *(unsigned*)&a, ub = *(unsigned*)&b, uc = *(unsigned*)&c, ud = *(unsigned*)&d;
    asm volatile("red.global.add.noftz.v4.f16x2 [%0], {%1,%2,%3,%4};"
                 :: "l"(p), "r"(ua), "r"(ub), "r"(uc), "r"(ud) : "memory");
}
__device__ __forceinline__ float tf32r(float x) {
    unsigned u;
    asm("cvt.rna.tf32.f32 %0, %1;" : "=r"(u) : "f"(x));
    return __uint_as_float(u);
}
__device__ __forceinline__ void mma_tf32(float c[4], unsigned a0, unsigned a1, unsigned a2,
                                         unsigned a3, unsigned b0, unsigned b1) {
    asm("mma.sync.aligned.m16n8k8.row.col.f32.tf32.tf32.f32 "
        "{%0,%1,%2,%3}, {%4,%5,%6,%7}, {%8,%9}, {%0,%1,%2,%3};"
        : "+f"(c[0]), "+f"(c[1]), "+f"(c[2]), "+f"(c[3])
        : "r"(a0), "r"(a1), "r"(a2), "r"(a3), "r"(b0), "r"(b1));
}
__device__ __forceinline__ float4 unpack4h(float2 r) { // 4 halves (as float2 bits) -> 4 floats
    __half2 h01 = *(__half2*)&r.x;
    __half2 h23 = *(__half2*)&r.y;
    float2 f01 = __half22float2(h01);
    float2 f23 = __half22float2(h23);
    return make_float4(f01.x, f01.y, f23.x, f23.y);
}
__device__ __forceinline__ float2 pack4h(float4 v) {   // 4 floats -> 4 halves as float2 bits
    __half2 p01 = __floats2half2_rn(v.x, v.y);
    __half2 p23 = __floats2half2_rn(v.z, v.w);
    float2 r;
    r.x = __uint_as_float(*(unsigned*)&p01);
    r.y = __uint_as_float(*(unsigned*)&p23);
    return r;
}

// ---------------- kernels ----------------
// FUSED: zero fp16 accumulators + build X16 (threads < NHF4), weighted-degree atomics
// (threads < N_EDGES). g_deg is zeroed beforehand by cudaMemsetAsync.
__global__ void prep_deg_kernel(const float* __restrict__ X,
                                const int* __restrict__ src, const int* __restrict__ dst,
                                const float* __restrict__ ew) {
    int i = blockIdx.x * blockDim.x + threadIdx.x;
    if (i < NHF4) {
        float4 z = make_float4(0.f, 0.f, 0.f, 0.f);
        ((float4*)g_T1o16)[i] = z;
        ((float4*)g_T1i16)[i] = z;
        ((float4*)g_P2o16)[i] = z;
        ((float4*)g_P2i16)[i] = z;
        float2 lo = pack4h(((const float4*)X)[2 * i]);
        float2 hi = pack4h(((const float4*)X)[2 * i + 1]);
        ((float4*)g_X16)[i] = make_float4(lo.x, lo.y, hi.x, hi.y);
    }
    if (i < N_EDGES) {
        float w = ew[i];
        atomicAdd(&g_deg[src[i]], w);
        atomicAdd(&g_deg[N_NODES + dst[i]], w);
    }
}

// FUSED: pack {src, dst, norm_out, norm_in} per edge (all threads) + W_eff build
// (threads < 2*DFEAT*F = 10240).
__global__ void pack_wprep_kernel(const int* __restrict__ src, const int* __restrict__ dst,
                                  const float* __restrict__ ew,
                                  const float* __restrict__ Wz, const float* __restrict__ Wh) {
    int e = blockIdx.x * blockDim.x + threadIdx.x;
    if (e < N_EDGES) {
        int s = src[e], d = dst[e];
        float w = ew[e];
        float no = w / g_deg[s];
        float ni = w / g_deg[N_NODES + d];
        g_eP[e] = make_int4(s, d, __float_as_int(no), __float_as_int(ni));
    }
    if (e < 2 * DFEAT * F) {
        int idx = e;
        int gate = idx / (DFEAT * F);
        int rem  = idx % (DFEAT * F);
        int f = rem / F, j = rem % F;
        int seg = f >> 5, r = f & 31;
        const float* W = gate ? Wh : Wz;
        float v;
        if (seg == 0)      v = W[(0 * 64 + r) * 32 + j] + W[(3 * 64 + r) * 32 + j]
                             - W[(2 * 64 + r) * 32 + j] - W[(5 * 64 + r) * 32 + j];
        else if (seg == 1) v = W[(1 * 64 + r) * 32 + j];
        else if (seg == 2) v = W[(4 * 64 + r) * 32 + j];
        else if (seg == 3) v = 2.f * W[(2 * 64 + r) * 32 + j];
        else               v = 2.f * W[(5 * 64 + r) * 32 + j];
        g_W[f * 64 + gate * 32 + j] = v;
    }
}

// hop 1, ILP=2, fp16 gathers from X16 (proven prop2 shape).
__global__ void prop1_kernel() {
    long idx = (long)blockIdx.x * blockDim.x + threadIdx.x;
    int e0 = (int)(idx >> 3);
    if (e0 >= EHALF) return;
    int e1 = e0 + EHALF;
    int h = (int)(idx & 7);
    int dir = h >> 2, l = h & 3;
    int4 epA = g_eP[e0];
    int4 epB = g_eP[e1];
    if (dir == 0) {
        float noA = __int_as_float(epA.z);
        float noB = __int_as_float(epB.z);
        float4 rA = ((const float4*)g_X16)[epA.x * 4 + l];
        float4 rB = ((const float4*)g_X16)[epB.x * 4 + l];
        float4 fA01 = unpack4h(make_float2(rA.x, rA.y));
        float4 fA23 = unpack4h(make_float2(rA.z, rA.w));
        float4 fB01 = unpack4h(make_float2(rB.x, rB.y));
        float4 fB23 = unpack4h(make_float2(rB.z, rB.w));
        red4h(&g_T1o16[epA.y * F + 8 * l],
              __floats2half2_rn(fA01.x * noA, fA01.y * noA),
              __floats2half2_rn(fA01.z * noA, fA01.w * noA),
              __floats2half2_rn(fA23.x * noA, fA23.y * noA),
              __floats2half2_rn(fA23.z * noA, fA23.w * noA));
        red4h(&g_T1o16[epB.y * F + 8 * l],
              __floats2half2_rn(fB01.x * noB, fB01.y * noB),
              __floats2half2_rn(fB01.z * noB, fB01.w * noB),
              __floats2half2_rn(fB23.x * noB, fB23.y * noB),
              __floats2half2_rn(fB23.z * noB, fB23.w * noB));
    } else {
        float niA = __int_as_float(epA.w);
        float niB = __int_as_float(epB.w);
        float4 rA = ((const float4*)g_X16)[epA.y * 4 + l];
        float4 rB = ((const float4*)g_X16)[epB.y * 4 + l];
        float4 fA01 = unpack4h(make_float2(rA.x, rA.y));
        float4 fA23 = unpack4h(make_float2(rA.z, rA.w));
        float4 fB01 = unpack4h(make_float2(rB.x, rB.y));
        float4 fB23 = unpack4h(make_float2(rB.z, rB.w));
        red4h(&g_T1i16[epA.x * F + 8 * l],
              __floats2half2_rn(fA01.x * niA, fA01.y * niA),
              __floats2half2_rn(fA01.z * niA, fA01.w * niA),
              __floats2half2_rn(fA23.x * niA, fA23.y * niA),
              __floats2half2_rn(fA23.z * niA, fA23.w * niA));
        red4h(&g_T1i16[epB.x * F + 8 * l],
              __floats2half2_rn(fB01.x * niB, fB01.y * niB),
              __floats2half2_rn(fB01.z * niB, fB01.w * niB),
              __floats2half2_rn(fB23.x * niB, fB23.y * niB),
              __floats2half2_rn(fB23.z * niB, fB23.w * niB));
    }
}

// hop 2, ILP=2: fp16 gathers (one 16B load = 8 features).
__global__ void prop2_kernel() {
    long idx = (long)blockIdx.x * blockDim.x + threadIdx.x;
    int e0 = (int)(idx >> 3);
    if (e0 >= EHALF) return;
    int e1 = e0 + EHALF;
    int h = (int)(idx & 7);
    int dir = h >> 2, l = h & 3;
    int4 epA = g_eP[e0];
    int4 epB = g_eP[e1];
    if (dir == 0) {
        float noA = __int_as_float(epA.z);
        float noB = __int_as_float(epB.z);
        float4 rA = ((const float4*)g_T1o16)[epA.x * 4 + l];
        float4 rB = ((const float4*)g_T1o16)[epB.x * 4 + l];
        float4 fA01 = unpack4h(make_float2(rA.x, rA.y));
        float4 fA23 = unpack4h(make_float2(rA.z, rA.w));
        float4 fB01 = unpack4h(make_float2(rB.x, rB.y));
        float4 fB23 = unpack4h(make_float2(rB.z, rB.w));
        red4h(&g_P2o16[epA.y * F + 8 * l],
              __floats2half2_rn(fA01.x * noA, fA01.y * noA),
              __floats2half2_rn(fA01.z * noA, fA01.w * noA),
              __floats2half2_rn(fA23.x * noA, fA23.y * noA),
              __floats2half2_rn(fA23.z * noA, fA23.w * noA));
        red4h(&g_P2o16[epB.y * F + 8 * l],
              __floats2half2_rn(fB01.x * noB, fB01.y * noB),
              __floats2half2_rn(fB01.z * noB, fB01.w * noB),
              __floats2half2_rn(fB23.x * noB, fB23.y * noB),
              __floats2half2_rn(fB23.z * noB, fB23.w * noB));
    } else {
        float niA = __int_as_float(epA.w);
        float niB = __int_as_float(epB.w);
        float4 rA = ((const float4*)g_T1i16)[epA.y * 4 + l];
        float4 rB = ((const float4*)g_T1i16)[epB.y * 4 + l];
        float4 fA01 = unpack4h(make_float2(rA.x, rA.y));
        float4 fA23 = unpack4h(make_float2(rA.z, rA.w));
        float4 fB01 = unpack4h(make_float2(rB.x, rB.y));
        float4 fB23 = unpack4h(make_float2(rB.z, rB.w));
        red4h(&g_P2i16[epA.x * F + 8 * l],
              __floats2half2_rn(fA01.x * niA, fA01.y * niA),
              __floats2half2_rn(fA01.z * niA, fA01.w * niA),
              __floats2half2_rn(fA23.x * niA, fA23.y * niA),
              __floats2half2_rn(fA23.z * niA, fA23.w * niA));
        red4h(&g_P2i16[epB.x * F + 8 * l],
              __floats2half2_rn(fB01.x * niB, fB01.y * niB),
              __floats2half2_rn(fB01.z * niB, fB01.w * niB),
              __floats2half2_rn(fB23.x * niB, fB23.y * niB),
              __floats2half2_rn(fB23.z * niB, fB23.w * niB));
    }
}

// ---------------- tensor-core GEMM + fused GRU epilogue ----------------
// [BM x 160] @ [160 x 64] via mma.sync.m16n8k8.tf32. ALL segments read fp16
// (seg 0 = X16 mirror; fp16 -> tf32 exact), uniform A-loader.
__global__ __launch_bounds__(128) void gemm_kernel(
    const float* __restrict__ bz, const float* __restrict__ bh,
    const float* __restrict__ wl, const float* __restrict__ bl,
    float* __restrict__ out)
{
    __shared__ __align__(16) float As[BM][36];   // [m][k]
    __shared__ __align__(16) float Bs[32][72];   // [k][n]

    int tid  = threadIdx.x;
    int w    = tid >> 5;
    int lane = tid & 31;
    int g    = lane >> 2;      // 0..7
    int tg   = lane & 3;       // 0..3
    int blockm = blockIdx.x * BM;

    float c[2][8][4];
#pragma unroll
    for (int mf = 0; mf < 2; mf++)
#pragma unroll
        for (int n = 0; n < 8; n++)
#pragma unroll
            for (int k = 0; k < 4; k++) c[mf][n][k] = 0.f;

    const __half* seg16[5] = { g_X16, g_T1o16, g_T1i16, g_P2o16, g_P2i16 };

    for (int ks = 0; ks < 5; ks++) {
        const __half* A = seg16[ks];
        // A tile: 128 nodes x 32 feats, fp16 -> f32 (tf32-exact)
#pragma unroll
        for (int i = 0; i < 8; i++) {
            int idx = i * 128 + tid;          // 0..1023
            int m  = idx >> 3;
            int f4 = idx & 7;
            int node = blockm + m;
            float2 r = (node < N_NODES) ? ((const float2*)A)[node * 8 + f4]
                                        : make_float2(0.f, 0.f);
            *(float4*)&As[m][f4 * 4] = unpack4h(r);
        }
        // B tile: 32 x 64, tf32-rounded
#pragma unroll
        for (int i = 0; i < 4; i++) {
            int fidx = i * 128 + tid;         // float4 idx, 0..511
            float4 v = ((const float4*)g_W)[ks * 512 + fidx];
            int r  = fidx >> 4;
            int c4 = (fidx & 15) * 4;
            float4 t = make_float4(tf32r(v.x), tf32r(v.y), tf32r(v.z), tf32r(v.w));
            *(float4*)&Bs[r][c4] = t;
        }
        __syncthreads();

#pragma unroll
        for (int kst = 0; kst < 4; kst++) {
            int kb = kst * 8;
            unsigned a[2][4];
#pragma unroll
            for (int mf = 0; mf < 2; mf++) {
                int mb = w * 32 + mf * 16;
                a[mf][0] = __float_as_uint(As[mb + g    ][kb + tg    ]);
                a[mf][1] = __float_as_uint(As[mb + g + 8][kb + tg    ]);
                a[mf][2] = __float_as_uint(As[mb + g    ][kb + tg + 4]);
                a[mf][3] = __float_as_uint(As[mb + g + 8][kb + tg + 4]);
            }
#pragma unroll
            for (int n = 0; n < 8; n++) {
                unsigned b0 = __float_as_uint(Bs[kb + tg    ][n * 8 + g]);
                unsigned b1 = __float_as_uint(Bs[kb + tg + 4][n * 8 + g]);
                mma_tf32(c[0][n], a[0][0], a[0][1], a[0][2], a[0][3], b0, b1);
                mma_tf32(c[1][n], a[1][0], a[1][1], a[1][2], a[1][3], b0, b1);
            }
        }
        __syncthreads();
    }

    // epilogue. col = n*8 + 2*tg + cc; rows g / g+8.  n<4: z gates, n+4: matching h gates.
    float bzv[4][2], bhv[4][2], wlv[4][2];
#pragma unroll
    for (int n = 0; n < 4; n++)
#pragma unroll
        for (int cc = 0; cc < 2; cc++) {
            int col = n * 8 + 2 * tg + cc;
            bzv[n][cc] = bz[col];
            bhv[n][cc] = bh[col];
            wlv[n][cc] = wl[col];
        }
    float bl0 = bl[0];

#pragma unroll
    for (int mf = 0; mf < 2; mf++) {
#pragma unroll
        for (int rh = 0; rh < 2; rh++) {
            float y = 0.f;
#pragma unroll
            for (int n = 0; n < 4; n++) {
#pragma unroll
                for (int cc = 0; cc < 2; cc++) {
                    float gz = c[mf][n    ][rh * 2 + cc] + bzv[n][cc];
                    float gh = c[mf][n + 4][rh * 2 + cc] + bhv[n][cc];
                    float z  = 1.f / (1.f + expf(-gz));
                    float ht = tanhf(gh);
                    float Hv = (1.f - z) * ht;
                    y += fmaxf(Hv, 0.f) * wlv[n][cc];
                }
            }
            y += __shfl_xor_sync(0xffffffffu, y, 1);
            y += __shfl_xor_sync(0xffffffffu, y, 2);
            if (tg == 0) {
                int node = blockm + w * 32 + mf * 16 + rh * 8 + g;
                if (node < N_NODES) out[node] = y + bl0;
            }
        }
    }
}

// ---------------- launch ----------------
extern "C" void kernel_launch(void* const* d_in, const int* in_sizes, int n_in,
                              void* d_out, int out_size) {
    const float* x  = (const float*)d_in[0];
    const int*   ei = (const int*)d_in[1];
    const float* ew = (const float*)d_in[2];
    const float* Wz = (const float*)d_in[5];
    const float* bz = (const float*)d_in[6];
    const float* Wh = (const float*)d_in[9];
    const float* bh = (const float*)d_in[10];
    const float* Wl = (const float*)d_in[11];
    const float* bl = (const float*)d_in[12];
    float* out = (float*)d_out;

    const int* src = ei;
    const int* dst = ei + N_EDGES;

    void* p_deg;
    cudaGetSymbolAddress(&p_deg, g_deg);
    cudaMemsetAsync(p_deg, 0, 2 * N_NODES * sizeof(float), 0);

    prep_deg_kernel<<<(N_EDGES + 255) / 256, 256>>>(x, src, dst, ew);
    pack_wprep_kernel<<<(N_EDGES + 255) / 256, 256>>>(src, dst, ew, Wz, Wh);
    prop1_kernel<<<(EHALF * 8 + 255) / 256, 256>>>();
    prop2_kernel<<<(EHALF * 8 + 255) / 256, 256>>>();
    gemm_kernel<<<(N_NODES + BM - 1) / BM, 128>>>(bz, bh, Wl, bl, out);
}

// round 16
// speedup vs baseline: 1.0356x; 1.0129x over previous
#include <cuda_runtime.h>
#include <cuda_fp16.h>
#include <math.h>

#define N_NODES 100000
#define N_EDGES 1000000
#define EHALF   (N_EDGES / 2)
#define F 32
#define DFEAT 160            // 5 segments x 32
#define BM 128               // GEMM M tile
#define NHF4 (N_NODES * F / 8)   // float4 count per fp16 [N,F] array = 400000

// ---------------- scratch (device globals; no allocation) ----------------
__device__ __align__(16) float  g_deg[2 * N_NODES];        // [deg_out | deg_in]
__device__ __align__(16) int4   g_eP[N_EDGES];             // {src, dst, no_h2, ni_h2}
__device__ __align__(16) __half g_X16 [N_NODES * F];       // fp16 mirror of X
__device__ __align__(16) __half g_T1o16[N_NODES * F];      // fp16 accumulators (hop 1)
__device__ __align__(16) __half g_T1i16[N_NODES * F];
__device__ __align__(16) __half g_P2o16[N_NODES * F];      // fp16 accumulators (hop 2)
__device__ __align__(16) __half g_P2i16[N_NODES * F];
__device__ __align__(16) float  g_W[DFEAT * 64];           // [f][64]: cols 0-31 Wz_eff, 32-63 Wh_eff

// ---------------- helpers ----------------
// 16-byte fp16 vector reduction: adds 8 halves in one L2 atomic op (sm_90+)
__device__ __forceinline__ void red4h(__half* p, __half2 a, __half2 b, __half2 c, __half2 d) {
    unsigned ua = *(unsigned*)&a, ub = *(unsigned*)&b, uc = *(unsigned*)&c, ud = *(unsigned*)&d;
    asm volatile("red.global.add.noftz.v4.f16x2 [%0], {%1,%2,%3,%4};"
                 :: "l"(p), "r"(ua), "r"(ub), "r"(uc), "r"(ud) : "memory");
}
// scale a gathered 16B fp16 row (float4 = 4x half2) by a broadcast half2 and reduce
__device__ __forceinline__ void scale_red(__half* p, float4 r, unsigned nbits) {
    __half2 nh = *(__half2*)&nbits;
    __half2 a = __hmul2(*(__half2*)&r.x, nh);
    __half2 b = __hmul2(*(__half2*)&r.y, nh);
    __half2 c = __hmul2(*(__half2*)&r.z, nh);
    __half2 d = __hmul2(*(__half2*)&r.w, nh);
    red4h(p, a, b, c, d);
}
__device__ __forceinline__ float tf32r(float x) {
    unsigned u;
    asm("cvt.rna.tf32.f32 %0, %1;" : "=r"(u) : "f"(x));
    return __uint_as_float(u);
}
__device__ __forceinline__ void mma_tf32(float c[4], unsigned a0, unsigned a1, unsigned a2,
                                         unsigned a3, unsigned b0, unsigned b1) {
    asm("mma.sync.aligned.m16n8k8.row.col.f32.tf32.tf32.f32 "
        "{%0,%1,%2,%3}, {%4,%5,%6,%7}, {%8,%9}, {%0,%1,%2,%3};"
        : "+f"(c[0]), "+f"(c[1]), "+f"(c[2]), "+f"(c[3])
        : "r"(a0), "r"(a1), "r"(a2), "r"(a3), "r"(b0), "r"(b1));
}
__device__ __forceinline__ float4 unpack4h(float2 r) { // 4 halves (as float2 bits) -> 4 floats
    __half2 h01 = *(__half2*)&r.x;
    __half2 h23 = *(__half2*)&r.y;
    float2 f01 = __half22float2(h01);
    float2 f23 = __half22float2(h23);
    return make_float4(f01.x, f01.y, f23.x, f23.y);
}
__device__ __forceinline__ float2 pack4h(float4 v) {   // 4 floats -> 4 halves as float2 bits
    __half2 p01 = __floats2half2_rn(v.x, v.y);
    __half2 p23 = __floats2half2_rn(v.z, v.w);
    float2 r;
    r.x = __uint_as_float(*(unsigned*)&p01);
    r.y = __uint_as_float(*(unsigned*)&p23);
    return r;
}

// ---------------- kernels ----------------
// FUSED: zero fp16 accumulators + build X16 (threads < NHF4), weighted-degree atomics
// (threads < N_EDGES). g_deg is zeroed beforehand by cudaMemsetAsync.
__global__ void prep_deg_kernel(const float* __restrict__ X,
                                const int* __restrict__ src, const int* __restrict__ dst,
                                const float* __restrict__ ew) {
    int i = blockIdx.x * blockDim.x + threadIdx.x;
    if (i < NHF4) {
        float4 z = make_float4(0.f, 0.f, 0.f, 0.f);
        ((float4*)g_T1o16)[i] = z;
        ((float4*)g_T1i16)[i] = z;
        ((float4*)g_P2o16)[i] = z;
        ((float4*)g_P2i16)[i] = z;
        float2 lo = pack4h(((const float4*)X)[2 * i]);
        float2 hi = pack4h(((const float4*)X)[2 * i + 1]);
        ((float4*)g_X16)[i] = make_float4(lo.x, lo.y, hi.x, hi.y);
    }
    if (i < N_EDGES) {
        float w = ew[i];
        atomicAdd(&g_deg[src[i]], w);
        atomicAdd(&g_deg[N_NODES + dst[i]], w);
    }
}

// FUSED: pack {src, dst, no_h2, ni_h2} per edge (norms as broadcast half2) + W_eff build.
__global__ void pack_wprep_kernel(const int* __restrict__ src, const int* __restrict__ dst,
                                  const float* __restrict__ ew,
                                  const float* __restrict__ Wz, const float* __restrict__ Wh) {
    int e = blockIdx.x * blockDim.x + threadIdx.x;
    if (e < N_EDGES) {
        int s = src[e], d = dst[e];
        float w = ew[e];
        float no = w / g_deg[s];
        float ni = w / g_deg[N_NODES + d];
        __half2 noh = __float2half2_rn(no);
        __half2 nih = __float2half2_rn(ni);
        g_eP[e] = make_int4(s, d, *(int*)&noh, *(int*)&nih);
    }
    if (e < 2 * DFEAT * F) {
        int idx = e;
        int gate = idx / (DFEAT * F);
        int rem  = idx % (DFEAT * F);
        int f = rem / F, j = rem % F;
        int seg = f >> 5, r = f & 31;
        const float* W = gate ? Wh : Wz;
        float v;
        if (seg == 0)      v = W[(0 * 64 + r) * 32 + j] + W[(3 * 64 + r) * 32 + j]
                             - W[(2 * 64 + r) * 32 + j] - W[(5 * 64 + r) * 32 + j];
        else if (seg == 1) v = W[(1 * 64 + r) * 32 + j];
        else if (seg == 2) v = W[(4 * 64 + r) * 32 + j];
        else if (seg == 3) v = 2.f * W[(2 * 64 + r) * 32 + j];
        else               v = 2.f * W[(5 * 64 + r) * 32 + j];
        g_W[f * 64 + gate * 32 + j] = v;
    }
}

// hop 1, ILP=2, pure fp16 path: gather 16B of X16, HMUL2 by norm, vector-red.
__global__ void prop1_kernel() {
    long idx = (long)blockIdx.x * blockDim.x + threadIdx.x;
    int e0 = (int)(idx >> 3);
    if (e0 >= EHALF) return;
    int e1 = e0 + EHALF;
    int h = (int)(idx & 7);
    int dir = h >> 2, l = h & 3;
    int4 epA = g_eP[e0];
    int4 epB = g_eP[e1];
    if (dir == 0) {
        float4 rA = ((const float4*)g_X16)[epA.x * 4 + l];
        float4 rB = ((const float4*)g_X16)[epB.x * 4 + l];
        scale_red(&g_T1o16[epA.y * F + 8 * l], rA, (unsigned)epA.z);
        scale_red(&g_T1o16[epB.y * F + 8 * l], rB, (unsigned)epB.z);
    } else {
        float4 rA = ((const float4*)g_X16)[epA.y * 4 + l];
        float4 rB = ((const float4*)g_X16)[epB.y * 4 + l];
        scale_red(&g_T1i16[epA.x * F + 8 * l], rA, (unsigned)epA.w);
        scale_red(&g_T1i16[epB.x * F + 8 * l], rB, (unsigned)epB.w);
    }
}

// hop 2, ILP=2, pure fp16 path.
__global__ void prop2_kernel() {
    long idx = (long)blockIdx.x * blockDim.x + threadIdx.x;
    int e0 = (int)(idx >> 3);
    if (e0 >= EHALF) return;
    int e1 = e0 + EHALF;
    int h = (int)(idx & 7);
    int dir = h >> 2, l = h & 3;
    int4 epA = g_eP[e0];
    int4 epB = g_eP[e1];
    if (dir == 0) {
        float4 rA = ((const float4*)g_T1o16)[epA.x * 4 + l];
        float4 rB = ((const float4*)g_T1o16)[epB.x * 4 + l];
        scale_red(&g_P2o16[epA.y * F + 8 * l], rA, (unsigned)epA.z);
        scale_red(&g_P2o16[epB.y * F + 8 * l], rB, (unsigned)epB.z);
    } else {
        float4 rA = ((const float4*)g_T1i16)[epA.y * 4 + l];
        float4 rB = ((const float4*)g_T1i16)[epB.y * 4 + l];
        scale_red(&g_P2i16[epA.x * F + 8 * l], rA, (unsigned)epA.w);
        scale_red(&g_P2i16[epB.x * F + 8 * l], rB, (unsigned)epB.w);
    }
}

// ---------------- tensor-core GEMM + fused GRU epilogue ----------------
// [BM x 160] @ [160 x 64] via mma.sync.m16n8k8.tf32. ALL segments read fp16
// (seg 0 = X16 mirror; fp16 -> tf32 exact), uniform A-loader.
__global__ __launch_bounds__(128) void gemm_kernel(
    const float* __restrict__ bz, const float* __restrict__ bh,
    const float* __restrict__ wl, const float* __restrict__ bl,
    float* __restrict__ out)
{
    __shared__ __align__(16) float As[BM][36];   // [m][k]
    __shared__ __align__(16) float Bs[32][72];   // [k][n]

    int tid  = threadIdx.x;
    int w    = tid >> 5;
    int lane = tid & 31;
    int g    = lane >> 2;      // 0..7
    int tg   = lane & 3;       // 0..3
    int blockm = blockIdx.x * BM;

    float c[2][8][4];
#pragma unroll
    for (int mf = 0; mf < 2; mf++)
#pragma unroll
        for (int n = 0; n < 8; n++)
#pragma unroll
            for (int k = 0; k < 4; k++) c[mf][n][k] = 0.f;

    const __half* seg16[5] = { g_X16, g_T1o16, g_T1i16, g_P2o16, g_P2i16 };

    for (int ks = 0; ks < 5; ks++) {
        const __half* A = seg16[ks];
        // A tile: 128 nodes x 32 feats, fp16 -> f32 (tf32-exact)
#pragma unroll
        for (int i = 0; i < 8; i++) {
            int idx = i * 128 + tid;          // 0..1023
            int m  = idx >> 3;
            int f4 = idx & 7;
            int node = blockm + m;
            float2 r = (node < N_NODES) ? ((const float2*)A)[node * 8 + f4]
                                        : make_float2(0.f, 0.f);
            *(float4*)&As[m][f4 * 4] = unpack4h(r);
        }
        // B tile: 32 x 64, tf32-rounded
#pragma unroll
        for (int i = 0; i < 4; i++) {
            int fidx = i * 128 + tid;         // float4 idx, 0..511
            float4 v = ((const float4*)g_W)[ks * 512 + fidx];
            int r  = fidx >> 4;
            int c4 = (fidx & 15) * 4;
            float4 t = make_float4(tf32r(v.x), tf32r(v.y), tf32r(v.z), tf32r(v.w));
            *(float4*)&Bs[r][c4] = t;
        }
        __syncthreads();

#pragma unroll
        for (int kst = 0; kst < 4; kst++) {
            int kb = kst * 8;
            unsigned a[2][4];
#pragma unroll
            for (int mf = 0; mf < 2; mf++) {
                int mb = w * 32 + mf * 16;
                a[mf][0] = __float_as_uint(As[mb + g    ][kb + tg    ]);
                a[mf][1] = __float_as_uint(As[mb + g + 8][kb + tg    ]);
                a[mf][2] = __float_as_uint(As[mb + g    ][kb + tg + 4]);
                a[mf][3] = __float_as_uint(As[mb + g + 8][kb + tg + 4]);
            }
#pragma unroll
            for (int n = 0; n < 8; n++) {
                unsigned b0 = __float_as_uint(Bs[kb + tg    ][n * 8 + g]);
                unsigned b1 = __float_as_uint(Bs[kb + tg + 4][n * 8 + g]);
                mma_tf32(c[0][n], a[0][0], a[0][1], a[0][2], a[0][3], b0, b1);
                mma_tf32(c[1][n], a[1][0], a[1][1], a[1][2], a[1][3], b0, b1);
            }
        }
        __syncthreads();
    }

    // epilogue. col = n*8 + 2*tg + cc; rows g / g+8.  n<4: z gates, n+4: matching h gates.
    float bzv[4][2], bhv[4][2], wlv[4][2];
#pragma unroll
    for (int n = 0; n < 4; n++)
#pragma unroll
        for (int cc = 0; cc < 2; cc++) {
            int col = n * 8 + 2 * tg + cc;
            bzv[n][cc] = bz[col];
            bhv[n][cc] = bh[col];
            wlv[n][cc] = wl[col];
        }
    float bl0 = bl[0];

#pragma unroll
    for (int mf = 0; mf < 2; mf++) {
#pragma unroll
        for (int rh = 0; rh < 2; rh++) {
            float y = 0.f;
#pragma unroll
            for (int n = 0; n < 4; n++) {
#pragma unroll
                for (int cc = 0; cc < 2; cc++) {
                    float gz = c[mf][n    ][rh * 2 + cc] + bzv[n][cc];
                    float gh = c[mf][n + 4][rh * 2 + cc] + bhv[n][cc];
                    float z  = 1.f / (1.f + expf(-gz));
                    float ht = tanhf(gh);
                    float Hv = (1.f - z) * ht;
                    y += fmaxf(Hv, 0.f) * wlv[n][cc];
                }
            }
            y += __shfl_xor_sync(0xffffffffu, y, 1);
            y += __shfl_xor_sync(0xffffffffu, y, 2);
            if (tg == 0) {
                int node = blockm + w * 32 + mf * 16 + rh * 8 + g;
                if (node < N_NODES) out[node] = y + bl0;
            }
        }
    }
}

// ---------------- launch ----------------
extern "C" void kernel_launch(void* const* d_in, const int* in_sizes, int n_in,
                              void* d_out, int out_size) {
    const float* x  = (const float*)d_in[0];
    const int*   ei = (const int*)d_in[1];
    const float* ew = (const float*)d_in[2];
    const float* Wz = (const float*)d_in[5];
    const float* bz = (const float*)d_in[6];
    const float* Wh = (const float*)d_in[9];
    const float* bh = (const float*)d_in[10];
    const float* Wl = (const float*)d_in[11];
    const float* bl = (const float*)d_in[12];
    float* out = (float*)d_out;

    const int* src = ei;
    const int* dst = ei + N_EDGES;

    void* p_deg;
    cudaGetSymbolAddress(&p_deg, g_deg);
    cudaMemsetAsync(p_deg, 0, 2 * N_NODES * sizeof(float), 0);

    prep_deg_kernel<<<(N_EDGES + 255) / 256, 256>>>(x, src, dst, ew);
    pack_wprep_kernel<<<(N_EDGES + 255) / 256, 256>>>(src, dst, ew, Wz, Wh);
    prop1_kernel<<<(EHALF * 8 + 255) / 256, 256>>>();
    prop2_kernel<<<(EHALF * 8 + 255) / 256, 256>>>();
    gemm_kernel<<<(N_NODES + BM - 1) / BM, 128>>>(bz, bh, Wl, bl, out);
}